// round 3
// baseline (speedup 1.0000x reference)
#include <cuda_runtime.h>
#include <cstdint>

// out[o,m,n] = sum_{kh,j} w0[o,kh,j] * S[m, n+kh, j]       (n >= 1)
// out[o,m,0] = sum_{kh,j} w0[o,kh,j] * S0[m, kh, j]
//   S[m,r,j]  = A[m,r-4,j] + B[m,r-5,j]   (zero-padded in h)
//   S0[m,kh,j]= (kh>=4 ? A[kh-4] : 0) + (kh<=4 ? B[51+kh] : 0)
// Scratch: Sg[((m*14 + j)*80) + r], r in [0,63] = S rows, [64,72] = S0 rows.

__device__ __align__(16) float Sg[56 * 14 * 80];

__device__ __forceinline__ uint64_t pack2(float s) {
    uint64_t r;
    unsigned u = __float_as_uint(s);
    asm("mov.b64 %0, {%1, %1};" : "=l"(r) : "r"(u));
    return r;
}
__device__ __forceinline__ void ffma2(uint64_t& d, uint64_t a, uint64_t b) {
    asm("fma.rn.f32x2 %0, %1, %2, %0;" : "+l"(d) : "l"(a), "l"(b));
}
__device__ __forceinline__ float2 unpack2(uint64_t v) {
    unsigned lo, hi;
    asm("mov.b64 {%0, %1}, %2;" : "=r"(lo), "=r"(hi) : "l"(v));
    return make_float2(__uint_as_float(lo), __uint_as_float(hi));
}

// ───────────── Kernel 1: build S ─────────────
// grid (56 m, 7 jg), 160 threads; each thread ≤1 output row-elem (2x73 per block)
#define XP 68   // padded x row stride
__global__ __launch_bounds__(160)
void build_S_kernel(const float* __restrict__ x, const float* __restrict__ w1)
{
    __shared__ float xp[24 * XP];   // xp[i][r], r in [0,65]: xp[i][h+5] = x[i,m,h]
    __shared__ float w1s[24 * 28];
    const int m = blockIdx.x, jg = blockIdx.y, tid = threadIdx.x;

    for (int t = tid; t < 24 * XP; t += 160) xp[t] = 0.0f;
    for (int t = tid; t < 24 * 28; t += 160) w1s[t] = w1[t];
    __syncthreads();
    for (int t = tid; t < 24 * 56; t += 160) {
        const int i = t / 56, h = t % 56;
        xp[i * XP + 5 + h] = x[i * 3136 + m * 56 + h];
    }
    __syncthreads();

    if (tid < 146) {
        const int j = jg * 2 + tid / 73;
        const int r = tid % 73;
        float a = 0.0f;
        if (r < 64) {
            // S[r] = sum_i xp[i][r+1]*w1a[j] + xp[i][r]*w1b[j]  (branch-free)
            #pragma unroll
            for (int i = 0; i < 24; i++) {
                a = fmaf(xp[i * XP + r + 1], w1s[i * 28 + j],      a);
                a = fmaf(xp[i * XP + r],     w1s[i * 28 + 14 + j], a);
            }
        } else {
            const int kh = r - 64;
            if (kh >= 4) {
                #pragma unroll
                for (int i = 0; i < 24; i++)
                    a = fmaf(xp[i * XP + kh + 1], w1s[i * 28 + j], a);   // A[kh-4] -> pad idx kh+1
            }
            if (kh <= 4) {
                #pragma unroll
                for (int i = 0; i < 24; i++)
                    a = fmaf(xp[i * XP + kh + 56], w1s[i * 28 + 14 + j], a); // B[51+kh] -> pad idx kh+56
            }
        }
        Sg[(m * 14 + j) * 80 + r] = a;
    }
}

// ───────────── Kernel 2: contraction ─────────────
// grid (56 m, 12 og of 8 o, 2 nh of 28 n), block 112 = 28 n × 4 ow (2 o each)
__global__ __launch_bounds__(112)
void contract_kernel(const float* __restrict__ w0, float* __restrict__ out)
{
    __shared__ __align__(16) float Ssm[14 * 80];      // full S slice for this m (4.5KB)
    __shared__ __align__(16) float w0s[126 * 8];      // [k][o_local] (4KB)

    const int m  = blockIdx.x;
    const int og = blockIdx.y;          // 0..11
    const int nh = blockIdx.z;          // 0..1
    const int tid = threadIdx.x;

    // stage S slice: 280 float4, coalesced
    {
        const float4* __restrict__ sg4 = reinterpret_cast<const float4*>(Sg + m * 14 * 80);
        float4* s4 = reinterpret_cast<float4*>(Ssm);
        #pragma unroll
        for (int t = tid; t < 14 * 20; t += 112) s4[t] = sg4[t];
    }
    // stage w0 transposed: w0s[k*8 + ol] = w0[(og*8+ol)*126 + k]
    for (int t = tid; t < 126 * 8; t += 112) {
        const int ol = t & 7, k = t >> 3;
        w0s[t] = w0[(og * 8 + ol) * 126 + k];
    }
    __syncthreads();

    const int nl = tid % 28;
    const int ow = tid / 28;                 // 0..3 -> 2 o's each
    const int n  = nh * 28 + nl;
    const int rbase = (n == 0) ? 64 : n;

    const float* __restrict__ sp = Ssm + rbase;
    const uint64_t* __restrict__ wp = reinterpret_cast<const uint64_t*>(w0s) + ow;

    uint64_t acc = 0;
    #pragma unroll
    for (int kh = 0; kh < 9; kh++) {
        #pragma unroll
        for (int j = 0; j < 14; j++) {
            const uint64_t s2 = pack2(sp[j * 80 + kh]);
            ffma2(acc, wp[(kh * 14 + j) * 4], s2);
        }
    }

    const int ob = og * 8 + ow * 2;
    float* op = out + m * 56 + n;
    const float2 r = unpack2(acc);
    op[(ob + 0) * 3136] = r.x;
    op[(ob + 1) * 3136] = r.y;
}

extern "C" void kernel_launch(void* const* d_in, const int* in_sizes, int n_in,
                              void* d_out, int out_size)
{
    const float* x = (const float*)d_in[0];
    const float* w0;
    const float* w1;
    if (in_sizes[1] == 12096) { w0 = (const float*)d_in[1]; w1 = (const float*)d_in[2]; }
    else                      { w0 = (const float*)d_in[2]; w1 = (const float*)d_in[1]; }
    float* out = (float*)d_out;

    build_S_kernel<<<dim3(56, 7), 160>>>(x, w1);
    contract_kernel<<<dim3(56, 12, 2), 112>>>(w0, out);
}